// round 16
// baseline (speedup 1.0000x reference)
#include <cuda_runtime.h>
#include <cuda_bf16.h>
#include <math.h>
#include <stdint.h>

#define BB 4
#define CC 192
#define NN 4096
#define NHEADS 8
#define HD 24
#define PLENC 256

typedef unsigned long long u64;

// ---------------- device scratch ----------------
__device__ __align__(256) float g_xc[BB * NN * CC];
__device__ __align__(256) float g_t[BB * NN * CC];
__device__ __align__(256) float g_qkvs[BB * NN * 768];
__device__ __align__(256) float g_qs[BB * NHEADS * NN * HD];
__device__ __align__(256) float g_kvmap[BB * 16 * NN * HD];
__device__ __align__(256) float g_pooled[BB * PLENC * CC];
__device__ __align__(256) float g_kvp[BB * PLENC * 384];
__device__ __align__(256) float g_kpn[BB * NHEADS * PLENC * HD];
__device__ __align__(256) float g_vpn[BB * NHEADS * PLENC * HD];
__device__ __align__(256) float g_ao[BB * NN * CC];
__device__ __align__(256) float g_tmp[BB * NN * CC];
__device__ __align__(256) float g_bcat[768];
__device__ __align__(256) float g_cpb[32768 * NHEADS];
__device__ __align__(256) unsigned g_Wcph[12 * 72 * 192];
__device__ __align__(256) unsigned g_Wcpl[12 * 72 * 192];
__device__ __align__(256) unsigned g_Wfph[960 * 96];
__device__ __align__(256) unsigned g_Wfpl[960 * 96];
__device__ __align__(256) float g_lt2[NHEADS * 216];
__device__ __align__(256) float g_w2[BB * NHEADS * NN * 12];

// ---------------- bf16 helpers ----------------
__device__ __forceinline__ void split_bf(float x, float& hi, float& lo) {
    hi = __bfloat162float(__float2bfloat16_rn(x));
    lo = x - hi;
}
__device__ __forceinline__ unsigned pack_bf(float a, float b) {
    __nv_bfloat162 t = __floats2bfloat162_rn(a, b);
    return *reinterpret_cast<unsigned*>(&t);
}
__device__ __forceinline__ void mma16bf(float* d, const unsigned* a, const unsigned* b) {
    asm volatile(
        "mma.sync.aligned.m16n8k16.row.col.f32.bf16.bf16.f32 "
        "{%0,%1,%2,%3}, {%4,%5,%6,%7}, {%8,%9}, {%0,%1,%2,%3};"
        : "+f"(d[0]), "+f"(d[1]), "+f"(d[2]), "+f"(d[3])
        : "r"(a[0]), "r"(a[1]), "r"(a[2]), "r"(a[3]), "r"(b[0]), "r"(b[1]));
}
// ---------------- packed fp32 helpers (f32x2) ----------------
__device__ __forceinline__ u64 packf2(float a, float b) {
    u64 r;
    asm("mov.b64 %0, {%1, %2};" : "=l"(r) : "f"(a), "f"(b));
    return r;
}
__device__ __forceinline__ float2 unpackf2(u64 v) {
    float2 r;
    asm("mov.b64 {%0, %1}, %2;" : "=f"(r.x), "=f"(r.y) : "l"(v));
    return r;
}
__device__ __forceinline__ void ffma2(u64& d, u64 a, u64 b) {
    asm("fma.rn.f32x2 %0, %1, %2, %0;" : "+l"(d) : "l"(a), "l"(b));
}

// ---------------- prep ----------------
__global__ void k_prep(const float* __restrict__ qw, const float* __restrict__ qb,
                       const float* __restrict__ kvw, const float* __restrict__ kvb,
                       const float* __restrict__ srw, const float* __restrict__ srb,
                       const float* __restrict__ projw,
                       const float* __restrict__ lt, const float* __restrict__ w) {
    int idx = blockIdx.x * 256 + threadIdx.x;
    if (idx < 165888) {
        int o = idx % 192;
        int r = idx / 192;
        int rr = r % 72;
        int cc = r / 72;
        int t = rr >> 3, p = rr & 7;
        int c = cc * 16 + 2 * p;
        float w0 = w[(size_t)o * 1728 + c * 9 + t];
        float w1 = w[(size_t)o * 1728 + (c + 1) * 9 + t];
        float h0, l0, h1, l1;
        split_bf(w0, h0, l0);
        split_bf(w1, h1, l1);
        g_Wcph[idx] = pack_bf(h0, h1);
        g_Wcpl[idx] = pack_bf(l0, l1);
    }
    if (idx < 960 * 96) {
        int o = idx / 96, pr = idx - (idx / 96) * 96;
        int c = 2 * pr;
        float v0, v1;
        if (o < 192)      { v0 = qw[o * 192 + c];          v1 = qw[o * 192 + c + 1]; }
        else if (o < 576) { v0 = kvw[(o - 192) * 192 + c]; v1 = kvw[(o - 192) * 192 + c + 1]; }
        else if (o < 768) { v0 = srw[(o - 576) * 192 + c]; v1 = srw[(o - 576) * 192 + c + 1]; }
        else              { v0 = projw[(o - 768) * 192 + c]; v1 = projw[(o - 768) * 192 + c + 1]; }
        float h0, l0, h1, l1;
        split_bf(v0, h0, l0);
        split_bf(v1, h1, l1);
        g_Wfph[idx] = pack_bf(h0, h1);
        g_Wfpl[idx] = pack_bf(l0, l1);
    }
    if (idx < 768) {
        float v;
        if (idx < 192)      v = qb[idx];
        else if (idx < 576) v = kvb[idx - 192];
        else                v = srb[idx - 576];
        g_bcat[idx] = v;
    }
    if (idx < 1728) {
        int h = idx / 216;
        int r = idx - h * 216;
        int l = r / 24, d = r - l * 24;
        g_lt2[idx] = lt[h * 216 + d * 9 + l];
    }
}

__global__ void __launch_bounds__(256) k_prep_cpb(const float* __restrict__ tab,
                           const float* __restrict__ c1w, const float* __restrict__ c1b,
                           const float* __restrict__ c2w, const float* __restrict__ c2b,
                           int T) {
    __shared__ float s1w[1024], s1b[512], s2[512 * 8];
    int tid = threadIdx.x;
#pragma unroll
    for (int i = 0; i < 4; i++) s1w[tid + i * 256] = c1w[tid + i * 256];
#pragma unroll
    for (int i = 0; i < 2; i++) s1b[tid + i * 256] = c1b[tid + i * 256];
#pragma unroll
    for (int i = 0; i < 16; i++) {
        int idx = tid + i * 256;
        int j = idx >> 3, h = idx & 7;
        s2[idx] = c2w[h * 512 + j];
    }
    __syncthreads();
    int t = blockIdx.x * 256 + tid;
    if (t >= T || t >= 32768) return;
    float t0 = tab[2 * t], t1 = tab[2 * t + 1];
    float acc[8];
#pragma unroll
    for (int h = 0; h < 8; h++) acc[h] = 0.f;
    for (int j = 0; j < 512; j++) {
        float hv = fmaxf(t0 * s1w[2 * j] + t1 * s1w[2 * j + 1] + s1b[j], 0.f);
#pragma unroll
        for (int h = 0; h < 8; h++) acc[h] += hv * s2[j * 8 + h];
    }
#pragma unroll
    for (int h = 0; h < 8; h++) g_cpb[t * 8 + h] = acc[h] + c2b[h];
}

// ---------------- conv 3x3 as implicit GEMM (3xBF16 m16n8k16) ----------------
__global__ void __launch_bounds__(256) k_conv_tc(const float* __restrict__ x,
                                                 const float* __restrict__ bias) {
    extern __shared__ float sm[];
    unsigned* u_xh = (unsigned*)sm;
    unsigned* u_xl = u_xh + 2240;
    unsigned* u_wh = u_xl + 2240;
    unsigned* u_wl = u_wh + 5184;

    int b = blockIdx.x >> 5;
    int y0 = (blockIdx.x & 31) * 2;
    int ocg = blockIdx.y;
    int tid = threadIdx.x;
    int wid = tid >> 5, lane = tid & 31;
    int g = lane >> 2, tcol = lane & 3;
    int wm0 = (wid >> 1) * 32, wn0 = (wid & 1) * 32;

    float acc[2][4][4];
#pragma unroll
    for (int a = 0; a < 2; a++)
#pragma unroll
        for (int bq = 0; bq < 4; bq++)
#pragma unroll
            for (int c = 0; c < 4; c++) acc[a][bq][c] = 0.f;

    const float* xb = x + (size_t)b * 192 * 4096;

    for (int cc = 0; cc < 12; cc++) {
        int c0 = cc * 16;
#pragma unroll
        for (int i = 0; i < 2; i++) {
            int f = tid + i * 256;
            int p = f >> 6;
            int rem = f & 63;
            int r = rem >> 4, seg = rem & 15;
            int gy = y0 - 1 + r;
            float4 v0 = make_float4(0.f, 0.f, 0.f, 0.f);
            float4 v1 = make_float4(0.f, 0.f, 0.f, 0.f);
            if (gy >= 0 && gy < 64) {
                v0 = *(const float4*)(xb + ((size_t)(c0 + 2 * p) * 64 + gy) * 64 + seg * 4);
                v1 = *(const float4*)(xb + ((size_t)(c0 + 2 * p + 1) * 64 + gy) * 64 + seg * 4);
            }
            int off = p * 280 + r * 68 + 1 + seg * 4;
            float h0, l0, h1, l1;
            split_bf(v0.x, h0, l0); split_bf(v1.x, h1, l1);
            u_xh[off + 0] = pack_bf(h0, h1); u_xl[off + 0] = pack_bf(l0, l1);
            split_bf(v0.y, h0, l0); split_bf(v1.y, h1, l1);
            u_xh[off + 1] = pack_bf(h0, h1); u_xl[off + 1] = pack_bf(l0, l1);
            split_bf(v0.z, h0, l0); split_bf(v1.z, h1, l1);
            u_xh[off + 2] = pack_bf(h0, h1); u_xl[off + 2] = pack_bf(l0, l1);
            split_bf(v0.w, h0, l0); split_bf(v1.w, h1, l1);
            u_xh[off + 3] = pack_bf(h0, h1); u_xl[off + 3] = pack_bf(l0, l1);
        }
        if (tid < 64) {
            int p = tid >> 3;
            int rr = tid & 7;
            int r = rr >> 1, side = rr & 1;
            int off = p * 280 + r * 68 + (side ? 65 : 0);
            u_xh[off] = 0u; u_xl[off] = 0u;
        }
#pragma unroll
        for (int i = 0; i < 5; i++) {
            int f = tid + i * 256;
            if (f < 1152) {
                int krow = f >> 4, seg = f & 15;
                size_t src = ((size_t)(cc * 72) + krow) * 192 + ocg * 64 + seg * 4;
                int off = krow * 72 + seg * 4;
                *(uint4*)(u_wh + off) = *(const uint4*)(g_Wcph + src);
                *(uint4*)(u_wl + off) = *(const uint4*)(g_Wcpl + src);
            }
        }
        __syncthreads();

#pragma unroll
        for (int t = 0; t < 9; t++) {
            int dh = t / 3, dw = t - dh * 3;
            unsigned bh[4][2], bl[4][2];
#pragma unroll
            for (int nt = 0; nt < 4; nt++) {
                int o = wn0 + nt * 8 + g;
                int kr0 = (t * 8 + tcol) * 72 + o;
                int kr1 = (t * 8 + tcol + 4) * 72 + o;
                bh[nt][0] = u_wh[kr0];
                bl[nt][0] = u_wl[kr0];
                bh[nt][1] = u_wh[kr1];
                bl[nt][1] = u_wl[kr1];
            }
#pragma unroll
            for (int mt = 0; mt < 2; mt++) {
                int mbase = wm0 + mt * 16;
                int rA = (mbase >> 6) + dh;
                int col0 = (mbase & 63) + g + dw;
                int base0 = tcol * 280 + rA * 68 + col0;
                int base1 = (tcol + 4) * 280 + rA * 68 + col0;
                unsigned ah[4], al[4];
                ah[0] = u_xh[base0];
                ah[1] = u_xh[base0 + 8];
                ah[2] = u_xh[base1];
                ah[3] = u_xh[base1 + 8];
                al[0] = u_xl[base0];
                al[1] = u_xl[base0 + 8];
                al[2] = u_xl[base1];
                al[3] = u_xl[base1 + 8];
#pragma unroll
                for (int nt = 0; nt < 4; nt++) {
                    mma16bf(acc[mt][nt], al, bh[nt]);
                    mma16bf(acc[mt][nt], ah, bl[nt]);
                    mma16bf(acc[mt][nt], ah, bh[nt]);
                }
            }
        }
        __syncthreads();
    }
    const float* bb = bias + ocg * 64;
    size_t rowbase = (size_t)b * 4096 + (size_t)y0 * 64;
#pragma unroll
    for (int mt = 0; mt < 2; mt++) {
#pragma unroll
        for (int nt = 0; nt < 4; nt++) {
            int r0 = wm0 + mt * 16 + g;
            int cc2 = wn0 + nt * 8 + 2 * tcol;
            float b0v = bb[cc2], b1v = bb[cc2 + 1];
            float* o0 = g_xc + (rowbase + r0) * 192 + ocg * 64 + cc2;
            o0[0] = acc[mt][nt][0] + b0v;
            o0[1] = acc[mt][nt][1] + b1v;
            float* o1 = g_xc + (rowbase + r0 + 8) * 192 + ocg * 64 + cc2;
            o1[0] = acc[mt][nt][2] + b0v;
            o1[1] = acc[mt][nt][3] + b1v;
        }
    }
}

// ---------------- row LN ----------------
__global__ void k_ln_rows(const float* __restrict__ gam, const float* __restrict__ bet) {
    int row = blockIdx.x * 8 + (threadIdx.x >> 5);
    int lane = threadIdx.x & 31;
    const float* src = g_xc + (size_t)row * 192;
    float v[6];
    float s = 0.f, q = 0.f;
#pragma unroll
    for (int j = 0; j < 6; j++) {
        v[j] = src[lane + j * 32];
        s += v[j]; q += v[j] * v[j];
    }
#pragma unroll
    for (int off = 16; off; off >>= 1) {
        s += __shfl_xor_sync(0xffffffffu, s, off);
        q += __shfl_xor_sync(0xffffffffu, q, off);
    }
    float mean = s * (1.f / 192.f);
    float rstd = rsqrtf(q * (1.f / 192.f) - mean * mean + 1e-5f);
    float* dst = g_t + (size_t)row * 192;
#pragma unroll
    for (int j = 0; j < 6; j++) {
        int c = lane + j * 32;
        dst[c] = (v[j] - mean) * rstd * gam[c] + bet[c];
    }
}

// ---------------- generic GEMM (3xBF16 m16n8k16; W pre-packed) ----------------
template <int BN>
__global__ void __launch_bounds__(256) k_gemm_tc(const float* __restrict__ A,
                                                 const unsigned* __restrict__ Wph,
                                                 const unsigned* __restrict__ Wpl,
                                                 const float* __restrict__ bias,
                                                 float* __restrict__ C,
                                                 int M, int Nout) {
    constexpr int NT = BN / 16;
    extern __shared__ unsigned smu[];
    unsigned* Ash = smu;
    unsigned* Asl = Ash + 2560;
    unsigned* Wsh = Asl + 2560;
    unsigned* Wsl = Wsh + BN * 20;
    int m0 = blockIdx.x * 128, n0 = blockIdx.y * BN;
    int tid = threadIdx.x, wid = tid >> 5, lane = tid & 31;
    int g = lane >> 2, tcol = lane & 3;
    int wm0 = (wid >> 1) * 32, wn0 = (wid & 1) * (BN / 2);
    float acc[2][NT][4];
#pragma unroll
    for (int a = 0; a < 2; a++)
#pragma unroll
        for (int b = 0; b < NT; b++)
#pragma unroll
            for (int c = 0; c < 4; c++) acc[a][b][c] = 0.f;

    for (int kc = 0; kc < 192; kc += 32) {
#pragma unroll
        for (int i = 0; i < 4; i++) {
            int f = tid + i * 256;
            int row = f >> 3, seg = f & 7;
            float4 v = *(const float4*)(A + (size_t)(m0 + row) * 192 + kc + seg * 4);
            float h0, l0, h1, l1;
            int off = row * 20 + seg * 2;
            split_bf(v.x, h0, l0); split_bf(v.y, h1, l1);
            Ash[off] = pack_bf(h0, h1); Asl[off] = pack_bf(l0, l1);
            split_bf(v.z, h0, l0); split_bf(v.w, h1, l1);
            Ash[off + 1] = pack_bf(h0, h1); Asl[off + 1] = pack_bf(l0, l1);
        }
#pragma unroll
        for (int i = 0; i < (BN * 4 + 255) / 256; i++) {
            int f = tid + i * 256;
            if (f < BN * 4) {
                int row = f >> 2, seg = f & 3;
                size_t src = (size_t)(n0 + row) * 96 + (kc >> 1) + seg * 4;
                uint4 vh = *(const uint4*)(Wph + src);
                uint4 vl = *(const uint4*)(Wpl + src);
                int off = row * 20 + seg * 4;
                Wsh[off + 0] = vh.x; Wsh[off + 1] = vh.y; Wsh[off + 2] = vh.z; Wsh[off + 3] = vh.w;
                Wsl[off + 0] = vl.x; Wsl[off + 1] = vl.y; Wsl[off + 2] = vl.z; Wsl[off + 3] = vl.w;
            }
        }
        __syncthreads();
#pragma unroll
        for (int kk8 = 0; kk8 < 16; kk8 += 8) {
            unsigned bh[NT][2], bl[NT][2];
#pragma unroll
            for (int nt = 0; nt < NT; nt++) {
                int wr = (wn0 + nt * 8 + g) * 20;
                bh[nt][0] = Wsh[wr + kk8 + tcol];
                bl[nt][0] = Wsl[wr + kk8 + tcol];
                bh[nt][1] = Wsh[wr + kk8 + tcol + 4];
                bl[nt][1] = Wsl[wr + kk8 + tcol + 4];
            }
#pragma unroll
            for (int mt = 0; mt < 2; mt++) {
                int r = wm0 + mt * 16 + g;
                int ar = r * 20, ar8 = (r + 8) * 20;
                unsigned ah[4], al[4];
                ah[0] = Ash[ar + kk8 + tcol];
                ah[1] = Ash[ar8 + kk8 + tcol];
                ah[2] = Ash[ar + kk8 + tcol + 4];
                ah[3] = Ash[ar8 + kk8 + tcol + 4];
                al[0] = Asl[ar + kk8 + tcol];
                al[1] = Asl[ar8 + kk8 + tcol];
                al[2] = Asl[ar + kk8 + tcol + 4];
                al[3] = Asl[ar8 + kk8 + tcol + 4];
#pragma unroll
                for (int nt = 0; nt < NT; nt++) {
                    mma16bf(acc[mt][nt], al, bh[nt]);
                    mma16bf(acc[mt][nt], ah, bl[nt]);
                    mma16bf(acc[mt][nt], ah, bh[nt]);
                }
            }
        }
        __syncthreads();
    }
#pragma unroll
    for (int mt = 0; mt < 2; mt++)
#pragma unroll
        for (int nt = 0; nt < NT; nt++) {
            int r = m0 + wm0 + mt * 16 + g;
            int cc = n0 + wn0 + nt * 8 + 2 * tcol;
            float b0v = bias[cc], b1v = bias[cc + 1];
            C[(size_t)r * Nout + cc]           = acc[mt][nt][0] + b0v;
            C[(size_t)r * Nout + cc + 1]       = acc[mt][nt][1] + b1v;
            C[(size_t)(r + 8) * Nout + cc]     = acc[mt][nt][2] + b0v;
            C[(size_t)(r + 8) * Nout + cc + 1] = acc[mt][nt][3] + b1v;
        }
}

// ---------------- fused post ----------------
__global__ void k_post(const float* __restrict__ qe, const float* __restrict__ temp,
                       const float* __restrict__ seqscale) {
    int idx = blockIdx.x * 256 + threadIdx.x;
    int g = idx % 24;
    int bn = idx / 24;
    int n = bn & 4095; int b = bn >> 12;
    if (g < 8) {
        int h = g;
        const float4* q4 = (const float4*)(g_qkvs + (size_t)bn * 768 + h * 24);
        float v[24]; float s = 0.f;
#pragma unroll
        for (int i = 0; i < 6; i++) {
            float4 t = q4[i];
            v[4 * i] = t.x; v[4 * i + 1] = t.y; v[4 * i + 2] = t.z; v[4 * i + 3] = t.w;
        }
#pragma unroll
        for (int d = 0; d < 24; d++) s += v[d] * v[d];
        float rn = 1.f / fmaxf(sqrtf(s), 1e-12f);
        float sp = log1pf(expf(temp[h]));
        float ss = seqscale[n];
        size_t ob = ((size_t)(b * 8 + h) * 4096 + n) * 24;
        float qn[24];
        float4* qs4 = (float4*)(g_qs + ob);
#pragma unroll
        for (int i = 0; i < 6; i++) {
            float4 c;
            float a0 = v[4 * i] * rn, a1 = v[4 * i + 1] * rn;
            float a2 = v[4 * i + 2] * rn, a3 = v[4 * i + 3] * rn;
            c.x = (a0 + qe[h * 24 + 4 * i])     * sp * ss;
            c.y = (a1 + qe[h * 24 + 4 * i + 1]) * sp * ss;
            c.z = (a2 + qe[h * 24 + 4 * i + 2]) * sp * ss;
            c.w = (a3 + qe[h * 24 + 4 * i + 3]) * sp * ss;
            qs4[i] = c;
            qn[4 * i] = a0; qn[4 * i + 1] = a1; qn[4 * i + 2] = a2; qn[4 * i + 3] = a3;
        }
        size_t ob2 = ((size_t)(b * 8 + h) * 4096 + n) * 12;
        const float* ltr = g_lt2 + h * 216;
#pragma unroll
        for (int l = 0; l < 9; l++) {
            float p = 0.f;
#pragma unroll
            for (int d = 0; d < 24; d++) p += qn[d] * ltr[l * 24 + d];
            g_w2[ob2 + l] = p;
        }
    } else {
        int gg = g - 8;
        const float4* src4 = (const float4*)(g_qkvs + (size_t)bn * 768 + 192 + gg * 24);
        float v[24]; float s = 0.f;
#pragma unroll
        for (int i = 0; i < 6; i++) {
            float4 t = src4[i];
            v[4 * i] = t.x; v[4 * i + 1] = t.y; v[4 * i + 2] = t.z; v[4 * i + 3] = t.w;
        }
#pragma unroll
        for (int d = 0; d < 24; d++) s += v[d] * v[d];
        float rn = 1.f;
        if (gg < 8) rn = 1.f / fmaxf(sqrtf(s), 1e-12f);
        size_t ob = ((size_t)(b * 16 + gg) * 4096 + n) * 24;
        float4* dst4 = (float4*)(g_kvmap + ob);
#pragma unroll
        for (int i = 0; i < 6; i++) {
            float4 o;
            o.x = v[4 * i] * rn; o.y = v[4 * i + 1] * rn;
            o.z = v[4 * i + 2] * rn; o.w = v[4 * i + 3] * rn;
            dst4[i] = o;
        }
    }
}

// ---------------- gelu + 4x4 pool + LN ----------------
__global__ void k_pool(const float* __restrict__ ng, const float* __restrict__ nb) {
    __shared__ float r1[192], r2[192];
    int b = blockIdx.y, m = blockIdx.x;
    int c = threadIdx.x;
    int ph = m >> 4, pw = m & 15;
    float acc = 0.f;
#pragma unroll
    for (int i = 0; i < 4; i++)
#pragma unroll
        for (int j = 0; j < 4; j++) {
            int n = (ph * 4 + i) * 64 + pw * 4 + j;
            float v = g_qkvs[((size_t)(b * 4096 + n)) * 768 + 576 + c];
            acc += 0.5f * v * (1.f + erff(v * 0.70710678118654752f));
        }
    acc *= (1.f / 16.f);
    r1[c] = acc; r2[c] = acc * acc;
    __syncthreads();
    if (c < 64) { r1[c] += r1[c + 64] + r1[c + 128]; r2[c] += r2[c + 64] + r2[c + 128]; }
    __syncthreads();
    for (int s2 = 32; s2 > 0; s2 >>= 1) {
        if (c < s2) { r1[c] += r1[c + s2]; r2[c] += r2[c + s2]; }
        __syncthreads();
    }
    float mean = r1[0] * (1.f / 192.f);
    float var = r2[0] * (1.f / 192.f) - mean * mean;
    float rstd = rsqrtf(var + 1e-5f);
    g_pooled[((size_t)(b * 256 + m)) * 192 + c] = (acc - mean) * rstd * ng[c] + nb[c];
}

// ---------------- post pooled kv ----------------
__global__ void k_postkvp() {
    int idx = blockIdx.x * 256 + threadIdx.x;
    int g = idx & 15; int bm = idx >> 4;
    int m = bm & 255; int b = bm >> 8;
    const float4* src4 = (const float4*)(g_kvp + (size_t)bm * 384 + g * 24);
    float v[24]; float s = 0.f;
#pragma unroll
    for (int i = 0; i < 6; i++) {
        float4 t = src4[i];
        v[4 * i] = t.x; v[4 * i + 1] = t.y; v[4 * i + 2] = t.z; v[4 * i + 3] = t.w;
    }
#pragma unroll
    for (int d = 0; d < 24; d++) s += v[d] * v[d];
    if (g < 8) {
        float rn = 1.f / fmaxf(sqrtf(s), 1e-12f);
        float4* dst4 = (float4*)(g_kpn + ((size_t)(b * 8 + g) * 256 + m) * 24);
#pragma unroll
        for (int i = 0; i < 6; i++) {
            float4 o;
            o.x = v[4 * i] * rn; o.y = v[4 * i + 1] * rn;
            o.z = v[4 * i + 2] * rn; o.w = v[4 * i + 3] * rn;
            dst4[i] = o;
        }
    } else {
        float4* dst4 = (float4*)(g_vpn + ((size_t)(b * 8 + g - 8) * 256 + m) * 24);
#pragma unroll
        for (int i = 0; i < 6; i++) {
            float4 o;
            o.x = v[4 * i]; o.y = v[4 * i + 1]; o.z = v[4 * i + 2]; o.w = v[4 * i + 3];
            dst4[i] = o;
        }
    }
}

// ---------------- fused attention (2 q/warp; f32x2 dots; register-resident logits;
//                   deferred normalization) ----------------
__global__ void __launch_bounds__(256) k_attn(const int* __restrict__ rel_idx,
                                              const float* __restrict__ rpb,
                                              const float* __restrict__ lb) {
    extern __shared__ float sm[];
    float* sk  = sm;
    float* skp = sk + 7776;
    float* svp = skp + 7168;
    float* slog = svp + 6240;
    float* srpb = slog + 4736;
    float* slb = srpb + 16;

    int b = blockIdx.z, h = blockIdx.y;
    int Y0 = (blockIdx.x >> 2) * 16, X0 = (blockIdx.x & 3) * 16;
    int tid = threadIdx.x;

    const float* kbase = g_kvmap + ((size_t)(b * 16 + h) * 4096) * 24;
    const float* vbase = g_kvmap + ((size_t)(b * 16 + 8 + h) * 4096) * 24;
    for (int f = tid; f < 1944; f += 256) {
        int r = f / 6, q = f - r * 6;
        int xx = r % 18, yy = r / 18;
        int gy = Y0 - 1 + yy, gx = X0 - 1 + xx;
        float4 v = make_float4(0.f, 0.f, 0.f, 0.f);
        if (gy >= 0 && gy < 64 && gx >= 0 && gx < 64)
            v = *(const float4*)(kbase + (size_t)(gy * 64 + gx) * 24 + q * 4);
        *(float4*)(sk + r * 24 + q * 4) = v;
    }
    const float* kp = g_kpn + (size_t)(b * 8 + h) * 256 * 24;
    const float* vp = g_vpn + (size_t)(b * 8 + h) * 256 * 24;
    for (int f = tid; f < 1536; f += 256) {
        int m = f / 6, q = f - m * 6;
        *(float4*)(skp + m * 28 + q * 4) = *(const float4*)(kp + m * 24 + q * 4);
    }
    for (int f = tid; f < 1024; f += 256) {
        int m = f >> 2, d = 24 + (f & 3);
        skp[m * 28 + d] = 0.f;
    }
    for (int f = tid; f < 1536; f += 256) {
        int m = f / 6, q = f - m * 6;
        float4 v = *(const float4*)(vp + (size_t)m * 24 + q * 4);
        svp[(q * 4 + 0) * 260 + m] = v.x;
        svp[(q * 4 + 1) * 260 + m] = v.y;
        svp[(q * 4 + 2) * 260 + m] = v.z;
        svp[(q * 4 + 3) * 260 + m] = v.w;
    }
    for (int f = tid; f < 96; f += 256) {
        int d = f >> 2, m = 256 + (f & 3);
        svp[d * 260 + m] = 0.f;
    }
    if (tid < 9) { srpb[tid] = rpb[h * 9 + tid]; slb[tid] = lb[h * 9 + tid]; }
    __syncthreads();

    int w = tid >> 5, ln = tid & 31;
    float* mylogA = slog + w * 296;   // [0..8] raw local e, [12..20] w2+lb, [32..287] raw pool e
    float* mylogB = slog + (8 + w) * 296;
    const unsigned FULL = 0xffffffffu;
    size_t bh4096 = (size_t)(b * 8 + h) * 4096;

    for (int it = 0; it < 16; it++) {
        int qiA = it * 16 + w;
        int qiB = qiA + 8;
        int tyA = qiA >> 4, txA = qiA & 15;
        int tyB = qiB >> 4, txB = qiB & 15;
        int gyA = Y0 + tyA, gxA = X0 + txA;
        int gyB = Y0 + tyB, gxB = X0 + txB;
        int nA = gyA * 64 + gxA, nB = gyB * 64 + gxB;

        // packed q pairs via uniform LDG (all lanes same address -> broadcast)
        const ulonglong2* qA2 = (const ulonglong2*)(g_qs + (bh4096 + nA) * 24);
        const ulonglong2* qB2 = (const ulonglong2*)(g_qs + (bh4096 + nB) * 24);
        u64 qpA[12], qpB[12];
#pragma unroll
        for (int i = 0; i < 6; i++) {
            ulonglong2 a = qA2[i], bq = qB2[i];
            qpA[2 * i] = a.x; qpA[2 * i + 1] = a.y;
            qpB[2 * i] = bq.x; qpB[2 * i + 1] = bq.y;
        }

        // local logits in registers (lanes 0..8 -> A, 16..24 -> B); -1e30 -> exp=0
        float ploc = -1e30f, wloc = 0.f;
        if (ln < 9) {
            wloc = g_w2[(bh4096 + nA) * 12 + ln] + slb[ln];
            int dh = ln / 3 - 1, dw = ln % 3 - 1;
            if ((gyA + dh >= 0) && (gyA + dh < 64) && (gxA + dw >= 0) && (gxA + dw < 64)) {
                const ulonglong2* kp2 = (const ulonglong2*)(sk + ((tyA + 1 + dh) * 18 + (txA + 1 + dw)) * 24);
                ulonglong2 c0 = kp2[0], c1 = kp2[1], c2 = kp2[2];
                ulonglong2 c3 = kp2[3], c4 = kp2[4], c5 = kp2[5];
                u64 acc = 0ULL;
                ffma2(acc, qpA[0], c0.x);  ffma2(acc, qpA[1], c0.y);
                ffma2(acc, qpA[2], c1.x);  ffma2(acc, qpA[3], c1.y);
                ffma2(acc, qpA[4], c2.x);  ffma2(acc, qpA[5], c2.y);
                ffma2(acc, qpA[6], c3.x);  ffma2(acc, qpA[7], c3.y);
                ffma2(acc, qpA[8], c4.x);  ffma2(acc, qpA[9], c4.y);
                ffma2(acc, qpA[10], c5.x); ffma2(acc, qpA[11], c5.y);
                float2 f2 = unpackf2(acc);
                ploc = f2.x + f2.y + srpb[ln];
            }
        } else if (ln >= 16 && ln < 25) {
            int l = ln - 16;
            wloc = g_w2[(bh4096 + nB) * 12 + l] + slb[l];
            int dh = l / 3 - 1, dw = l % 3 - 1;
            if ((gyB + dh >= 0) && (gyB + dh < 64) && (gxB + dw >= 0) && (gxB + dw < 64)) {
                const ulonglong2* kp2 = (const ulonglong2*)(sk + ((tyB + 1 + dh) * 18 + (txB + 1 + dw)) * 24);
                ulonglong2 c0 = kp2[0], c1 = kp2[1], c2 = kp2[2];
                ulonglong2 c3 = kp2[3], c4 = kp2[4], c5 = kp2[5];
                u64 acc = 0ULL;
                ffma2(acc, qpB[0], c0.x);  ffma2(acc, qpB[1], c0.y);
                ffma2(acc, qpB[2], c1.x);  ffma2(acc, qpB[3], c1.y);
                ffma2(acc, qpB[4], c2.x);  ffma2(acc, qpB[5], c2.y);
                ffma2(acc, qpB[6], c3.x);  ffma2(acc, qpB[7], c3.y);
                ffma2(acc, qpB[8], c4.x);  ffma2(acc, qpB[9], c4.y);
                ffma2(acc, qpB[10], c5.x); ffma2(acc, qpB[11], c5.y);
                float2 f2 = unpackf2(acc);
                ploc = f2.x + f2.y + srpb[l];
            }
        }

        // pool logits -> registers (8 per query per lane)
        const int* riA = rel_idx + (size_t)nA * 256;
        const int* riB = rel_idx + (size_t)nB * 256;
        float aA[8], aB[8];
#pragma unroll
        for (int bm = 0; bm < 8; bm++) {
            int m = bm * 32 + ln;
            float cA = g_cpb[(size_t)riA[m] * 8 + h];
            float cB = g_cpb[(size_t)riB[m] * 8 + h];
            const ulonglong2* rp = (const ulonglong2*)(skp + m * 28);
            ulonglong2 r0 = rp[0], r1 = rp[1], r2 = rp[2];
            ulonglong2 r3 = rp[3], r4 = rp[4], r5 = rp[5];
            u64 accA = 0ULL, accB = 0ULL;
            ffma2(accA, qpA[0], r0.x);  ffma2(accB, qpB[0], r0.x);
            ffma2(accA, qpA[1], r0.y);  ffma2(accB, qpB[1], r0.y);
            ffma2(accA, qpA[2], r1.x);  ffma2(accB, qpB[2], r1.x);
            ffma2(accA, qpA[3], r1.y);  ffma2(accB, qpB[3], r1.y);
            ffma2(accA, qpA[4], r2.x);  ffma2(accB, qpB[4], r2.x);
            ffma2(accA, qpA[5], r2.y);  ffma2(accB, qpB[5], r2.y);
            ffma2(accA, qpA[6], r3.x);  ffma2(accB, qpB[6], r3.x);
            ffma2(accA, qpA[7], r3.y);  ffma2(accB, qpB[7], r3.y);
            ffma2(accA, qpA[8], r4.x);  ffma2(accB, qpB[8], r4.x);
            ffma2(accA, qpA[9], r4.y);  ffma2(accB, qpB[9], r4.y);
            ffma2(accA, qpA[10], r5.x); ffma2(accB, qpB[10], r5.x);
            ffma2(accA, qpA[11], r5.y); ffma2(accB, qpB[11], r5.y);
            float2 fa = unpackf2(accA);
            float2 fb = unpackf2(accB);
            aA[bm] = fa.x + fa.y + cA;
            aB[bm] = fb.x + fb.y + cB;
        }

        // prefetch local V taps
        float vA[9], vB[9];
        if (ln < 24) {
#pragma unroll
            for (int l = 0; l < 9; l++) {
                int dh = l / 3 - 1, dw = l % 3 - 1;
                int nyA = gyA + dh, nxA = gxA + dw;
                vA[l] = (nyA >= 0 && nyA < 64 && nxA >= 0 && nxA < 64)
                        ? vbase[(size_t)(nyA * 64 + nxA) * 24 + ln] : 0.f;
                int nyB = gyB + dh, nxB = gxB + dw;
                vB[l] = (nyB >= 0 && nyB < 64 && nxB >= 0 && nxB < 64)
                        ? vbase[(size_t)(nyB * 64 + nxB) * 24 + ln] : 0.f;
            }
        }

        // register-resident softmax (max/exp/sum), deferred normalization
        float mxA = (ln < 9) ? ploc : -1e30f;
        float mxB = (ln >= 16 && ln < 25) ? ploc : -1e30f;
#pragma unroll
        for (int j = 0; j < 8; j++) {
            mxA = fmaxf(mxA, aA[j]);
            mxB = fmaxf(mxB, aB[j]);
        }
#pragma unroll
        for (int off = 16; off > 0; off >>= 1) {
            mxA = fmaxf(mxA, __shfl_xor_sync(FULL, mxA, off));
            mxB = fmaxf(mxB, __shfl_xor_sync(FULL, mxB, off));
        }
        float sumA = 0.f, sumB = 0.f;
#pragma unroll
        for (int j = 0; j < 8; j++) {
            float eA = expf(aA[j] - mxA);
            float eB = expf(aB[j] - mxB);
            mylogA[32 + j * 32 + ln] = eA;
            mylogB[32 + j * 32 + ln] = eB;
            sumA += eA;
            sumB += eB;
        }
        if (ln < 9) {
            float e = expf(ploc - mxA);
            mylogA[ln] = e;
            mylogA[12 + ln] = wloc;
            sumA += e;
        } else if (ln >= 16 && ln < 25) {
            float e = expf(ploc - mxB);
            mylogB[ln - 16] = e;
            mylogB[12 + ln - 16] = wloc;
            sumB += e;
        }
#pragma unroll
        for (int off = 16; off > 0; off >>= 1) {
            sumA += __shfl_xor_sync(FULL, sumA, off);
            sumB += __shfl_xor_sync(FULL, sumB, off);
        }
        float invA = 1.f / sumA, invB = 1.f / sumB;
        __syncwarp();

        if (ln < 24) {
            // local: Sum (w2+lb)·v  +  inv·Sum e·v
            float lwA = 0.f, lwB = 0.f, leA = 0.f, leB = 0.f;
#pragma unroll
            for (int l = 0; l < 9; l++) {
                lwA += mylogA[12 + l] * vA[l];
                leA += mylogA[l] * vA[l];
                lwB += mylogB[12 + l] * vB[l];
                leB += mylogB[l] * vB[l];
            }
            const float* vrow = svp + ln * 260;
            u64 pA0 = 0ULL, pA1 = 0ULL, pB0 = 0ULL, pB1 = 0ULL;
#pragma unroll
            for (int m = 0; m < 256; m += 8) {
                const ulonglong2* vp2 = (const ulonglong2*)(vrow + m);
                ulonglong2 v0 = vp2[0], v1 = vp2[1];
                const ulonglong2* wA2 = (const ulonglong2*)(mylogA + 32 + m);
                const ulonglong2* wB2 = (const ulonglong2*)(mylogB + 32 + m);
                ulonglong2 a0 = wA2[0], a1 = wA2[1];
                ulonglong2 b0 = wB2[0], b1 = wB2[1];
                ffma2(pA0, a0.x, v0.x); ffma2(pB0, b0.x, v0.x);
                ffma2(pA0, a0.y, v0.y); ffma2(pB0, b0.y, v0.y);
                ffma2(pA1, a1.x, v1.x); ffma2(pB1, b1.x, v1.x);
                ffma2(pA1, a1.y, v1.y); ffma2(pB1, b1.y, v1.y);
            }
            float2 fA0 = unpackf2(pA0), fA1 = unpackf2(pA1);
            float2 fB0 = unpackf2(pB0), fB1 = unpackf2(pB1);
            float poolA = (fA0.x + fA0.y) + (fA1.x + fA1.y);
            float poolB = (fB0.x + fB0.y) + (fB1.x + fB1.y);
            g_ao[((size_t)(b * 4096 + nA)) * 192 + h * 24 + ln] = lwA + invA * (leA + poolA);
            g_ao[((size_t)(b * 4096 + nB)) * 192 + h * 24 + ln] = lwB + invB * (leB + poolB);
        }
        __syncwarp();
    }
}

// ---------------- final LN + transpose to (B,C,N) ----------------
__global__ void k_lnout(const float* __restrict__ gam, const float* __restrict__ bet,
                        float* __restrict__ out) {
    __shared__ float s[192 * 33];
    __shared__ float red[2][8][32];
    __shared__ float smean[32], srstd[32];
    int b = blockIdx.y, n0 = blockIdx.x * 32;
    int tx = threadIdx.x & 31, ty = threadIdx.x >> 5;
    for (int idx = threadIdx.x; idx < 32 * 192; idx += 256) {
        int i = idx / 192, c = idx - i * 192;
        s[c * 33 + i] = g_tmp[((size_t)(b * 4096 + n0 + i)) * 192 + c];
    }
    __syncthreads();
    float sum = 0.f, sq = 0.f;
    for (int c = ty; c < 192; c += 8) {
        float v = s[c * 33 + tx];
        sum += v; sq += v * v;
    }
    red[0][ty][tx] = sum; red[1][ty][tx] = sq;
    __syncthreads();
    if (ty == 0) {
        float s1 = 0.f, s2 = 0.f;
#pragma unroll
        for (int k = 0; k < 8; k++) { s1 += red[0][k][tx]; s2 += red[1][k][tx]; }
        float m = s1 * (1.f / 192.f);
        float var = s2 * (1.f / 192.f) - m * m;
        smean[tx] = m; srstd[tx] = rsqrtf(var + 1e-5f);
    }
    __syncthreads();
    for (int c = ty; c < 192; c += 8)
        out[(size_t)(b * 192 + c) * 4096 + n0 + tx] =
            (s[c * 33 + tx] - smean[tx]) * srstd[tx] * gam[c] + bet[c];
}

// ---------------- launch ----------------
extern "C" void kernel_launch(void* const* d_in, const int* in_sizes, int n_in,
                              void* d_out, int out_size) {
    const float* x      = (const float*)d_in[0];
    const float* pe_w   = (const float*)d_in[1];
    const float* pe_b   = (const float*)d_in[2];
    const float* pe_ln_g= (const float*)d_in[3];
    const float* pe_ln_b= (const float*)d_in[4];
    const float* q_w    = (const float*)d_in[5];
    const float* q_b    = (const float*)d_in[6];
    const float* kv_w   = (const float*)d_in[7];
    const float* kv_b   = (const float*)d_in[8];
    const float* sr_w   = (const float*)d_in[9];
    const float* sr_b   = (const float*)d_in[10];
    const float* norm_g = (const float*)d_in[11];
    const float* norm_b = (const float*)d_in[12];
    const float* cpb1_w = (const float*)d_in[13];
    const float* cpb1_b = (const float*)d_in[14];
    const float* cpb2_w = (const float*)d_in[15];
    const float* cpb2_b = (const float*)d_in[16];
    const float* rpb    = (const float*)d_in[17];
    const float* lt     = (const float*)d_in[18];
    const float* lb     = (const float*)d_in[19];
    const float* qe     = (const float*)d_in[20];
    const float* temp   = (const float*)d_in[21];
    const float* proj_w = (const float*)d_in[22];
    const float* proj_b = (const float*)d_in[23];
    const float* oln_g  = (const float*)d_in[24];
    const float* oln_b  = (const float*)d_in[25];
    const int*   relidx = (const int*)d_in[26];
    const float* ctab   = (const float*)d_in[27];
    const float* sscale = (const float*)d_in[28];
    float* out = (float*)d_out;

    int T = in_sizes[27] / 2;

    float *p_t, *p_qkvs, *p_pooled, *p_ao, *p_tmp, *p_bcat, *p_kvp;
    unsigned *p_Wfph, *p_Wfpl;
    cudaGetSymbolAddress((void**)&p_t, g_t);
    cudaGetSymbolAddress((void**)&p_qkvs, g_qkvs);
    cudaGetSymbolAddress((void**)&p_pooled, g_pooled);
    cudaGetSymbolAddress((void**)&p_kvp, g_kvp);
    cudaGetSymbolAddress((void**)&p_ao, g_ao);
    cudaGetSymbolAddress((void**)&p_tmp, g_tmp);
    cudaGetSymbolAddress((void**)&p_bcat, g_bcat);
    cudaGetSymbolAddress((void**)&p_Wfph, g_Wfph);
    cudaGetSymbolAddress((void**)&p_Wfpl, g_Wfpl);

    int attn_smem = 25952 * 4;
    int conv_smem = 14848 * 4;
    int gemm128_smem = (2560 * 2 + 128 * 20 * 2) * 4;
    int gemm64_smem  = (2560 * 2 + 64 * 20 * 2) * 4;

    static cudaStream_t s1 = nullptr;
    static cudaEvent_t evFork = nullptr, evGemm = nullptr, evJoin = nullptr;
    if (!s1) {
        cudaStreamCreateWithFlags(&s1, cudaStreamNonBlocking);
        cudaEventCreateWithFlags(&evFork, cudaEventDisableTiming);
        cudaEventCreateWithFlags(&evGemm, cudaEventDisableTiming);
        cudaEventCreateWithFlags(&evJoin, cudaEventDisableTiming);
        cudaFuncSetAttribute(k_attn, cudaFuncAttributeMaxDynamicSharedMemorySize, attn_smem);
        cudaFuncSetAttribute(k_conv_tc, cudaFuncAttributeMaxDynamicSharedMemorySize, conv_smem);
        cudaFuncSetAttribute(k_gemm_tc<128>, cudaFuncAttributeMaxDynamicSharedMemorySize, gemm128_smem);
        cudaFuncSetAttribute(k_gemm_tc<64>, cudaFuncAttributeMaxDynamicSharedMemorySize, gemm64_smem);
    }

    // fork: cpb table on s1 overlaps the conv chain
    cudaEventRecord(evFork, 0);
    cudaStreamWaitEvent(s1, evFork, 0);
    k_prep_cpb<<<(T + 255) / 256, 256, 0, s1>>>(ctab, cpb1_w, cpb1_b, cpb2_w, cpb2_b, T);

    k_prep<<<1296, 256>>>(q_w, q_b, kv_w, kv_b, sr_w, sr_b, proj_w, lt, pe_w);
    k_conv_tc<<<dim3(128, 3), 256, conv_smem>>>(x, pe_b);
    k_ln_rows<<<2048, 256>>>(pe_ln_g, pe_ln_b);
    k_gemm_tc<128><<<dim3(128, 6), 256, gemm128_smem>>>(p_t, p_Wfph, p_Wfpl, p_bcat, p_qkvs, 16384, 768);

    // fork: pool chain on s1 overlaps k_post on main
    cudaEventRecord(evGemm, 0);
    cudaStreamWaitEvent(s1, evGemm, 0);
    k_pool<<<dim3(256, 4), 192, 0, s1>>>(norm_g, norm_b);
    k_gemm_tc<128><<<dim3(8, 3), 256, gemm128_smem, s1>>>(p_pooled, p_Wfph + 192 * 96, p_Wfpl + 192 * 96, kv_b, p_kvp, 1024, 384);
    k_postkvp<<<64, 256, 0, s1>>>();
    cudaEventRecord(evJoin, s1);

    k_post<<<1536, 256>>>(qe, temp, sscale);

    // join before attention
    cudaStreamWaitEvent(0, evJoin, 0);
    k_attn<<<dim3(16, 8, 4), 256, attn_smem>>>(relidx, rpb, lb);
    k_gemm_tc<64><<<dim3(128, 3), 256, gemm64_smem>>>(p_ao, p_Wfph + 768 * 96, p_Wfpl + 768 * 96, proj_b, p_tmp, 16384, 192);
    k_lnout<<<dim3(128, 4), 256>>>(oln_g, oln_b, out);
}

// round 17
// speedup vs baseline: 1.1014x; 1.1014x over previous
#include <cuda_runtime.h>
#include <cuda_bf16.h>
#include <math.h>
#include <stdint.h>

#define BB 4
#define CC 192
#define NN 4096
#define NHEADS 8
#define HD 24
#define PLENC 256

typedef unsigned long long u64;

// ---------------- device scratch ----------------
__device__ __align__(256) float g_xc[BB * NN * CC];
__device__ __align__(256) float g_t[BB * NN * CC];
__device__ __align__(256) float g_qkvs[BB * NN * 768];
__device__ __align__(256) float g_qs[BB * NHEADS * NN * HD];
__device__ __align__(256) float g_kvmap[BB * 16 * NN * HD];
__device__ __align__(256) float g_pooled[BB * PLENC * CC];
__device__ __align__(256) float g_kvp[BB * PLENC * 384];
__device__ __align__(256) float g_kpn[BB * NHEADS * PLENC * HD];
__device__ __align__(256) float g_vpn[BB * NHEADS * PLENC * HD];
__device__ __align__(256) float g_ao[BB * NN * CC];
__device__ __align__(256) float g_tmp[BB * NN * CC];
__device__ __align__(256) float g_bcat[768];
__device__ __align__(256) float g_cpb[32768 * NHEADS];
__device__ __align__(256) unsigned g_Wcph[12 * 72 * 192];
__device__ __align__(256) unsigned g_Wcpl[12 * 72 * 192];
__device__ __align__(256) unsigned g_Wfph[960 * 96];
__device__ __align__(256) unsigned g_Wfpl[960 * 96];
__device__ __align__(256) float g_lt2[NHEADS * 216];
__device__ __align__(256) float g_w2[BB * NHEADS * NN * 12];

// ---------------- bf16 helpers ----------------
__device__ __forceinline__ void split_bf(float x, float& hi, float& lo) {
    hi = __bfloat162float(__float2bfloat16_rn(x));
    lo = x - hi;
}
__device__ __forceinline__ unsigned pack_bf(float a, float b) {
    __nv_bfloat162 t = __floats2bfloat162_rn(a, b);
    return *reinterpret_cast<unsigned*>(&t);
}
__device__ __forceinline__ void mma16bf(float* d, const unsigned* a, const unsigned* b) {
    asm volatile(
        "mma.sync.aligned.m16n8k16.row.col.f32.bf16.bf16.f32 "
        "{%0,%1,%2,%3}, {%4,%5,%6,%7}, {%8,%9}, {%0,%1,%2,%3};"
        : "+f"(d[0]), "+f"(d[1]), "+f"(d[2]), "+f"(d[3])
        : "r"(a[0]), "r"(a[1]), "r"(a[2]), "r"(a[3]), "r"(b[0]), "r"(b[1]));
}
// ---------------- packed fp32 helpers (f32x2) ----------------
__device__ __forceinline__ u64 packf2(float a, float b) {
    u64 r;
    asm("mov.b64 %0, {%1, %2};" : "=l"(r) : "f"(a), "f"(b));
    return r;
}
__device__ __forceinline__ float2 unpackf2(u64 v) {
    float2 r;
    asm("mov.b64 {%0, %1}, %2;" : "=f"(r.x), "=f"(r.y) : "l"(v));
    return r;
}
__device__ __forceinline__ void ffma2(u64& d, u64 a, u64 b) {
    asm("fma.rn.f32x2 %0, %1, %2, %0;" : "+l"(d) : "l"(a), "l"(b));
}

// ---------------- prep ----------------
__global__ void k_prep(const float* __restrict__ qw, const float* __restrict__ qb,
                       const float* __restrict__ kvw, const float* __restrict__ kvb,
                       const float* __restrict__ srw, const float* __restrict__ srb,
                       const float* __restrict__ projw,
                       const float* __restrict__ lt, const float* __restrict__ w) {
    int idx = blockIdx.x * 256 + threadIdx.x;
    if (idx < 165888) {
        int o = idx % 192;
        int r = idx / 192;
        int rr = r % 72;
        int cc = r / 72;
        int t = rr >> 3, p = rr & 7;
        int c = cc * 16 + 2 * p;
        float w0 = w[(size_t)o * 1728 + c * 9 + t];
        float w1 = w[(size_t)o * 1728 + (c + 1) * 9 + t];
        float h0, l0, h1, l1;
        split_bf(w0, h0, l0);
        split_bf(w1, h1, l1);
        g_Wcph[idx] = pack_bf(h0, h1);
        g_Wcpl[idx] = pack_bf(l0, l1);
    }
    if (idx < 960 * 96) {
        int o = idx / 96, pr = idx - (idx / 96) * 96;
        int c = 2 * pr;
        float v0, v1;
        if (o < 192)      { v0 = qw[o * 192 + c];          v1 = qw[o * 192 + c + 1]; }
        else if (o < 576) { v0 = kvw[(o - 192) * 192 + c]; v1 = kvw[(o - 192) * 192 + c + 1]; }
        else if (o < 768) { v0 = srw[(o - 576) * 192 + c]; v1 = srw[(o - 576) * 192 + c + 1]; }
        else              { v0 = projw[(o - 768) * 192 + c]; v1 = projw[(o - 768) * 192 + c + 1]; }
        float h0, l0, h1, l1;
        split_bf(v0, h0, l0);
        split_bf(v1, h1, l1);
        g_Wfph[idx] = pack_bf(h0, h1);
        g_Wfpl[idx] = pack_bf(l0, l1);
    }
    if (idx < 768) {
        float v;
        if (idx < 192)      v = qb[idx];
        else if (idx < 576) v = kvb[idx - 192];
        else                v = srb[idx - 576];
        g_bcat[idx] = v;
    }
    if (idx < 1728) {
        int h = idx / 216;
        int r = idx - h * 216;
        int l = r / 24, d = r - l * 24;
        g_lt2[idx] = lt[h * 216 + d * 9 + l];
    }
}

__global__ void __launch_bounds__(256) k_prep_cpb(const float* __restrict__ tab,
                           const float* __restrict__ c1w, const float* __restrict__ c1b,
                           const float* __restrict__ c2w, const float* __restrict__ c2b,
                           int T) {
    __shared__ float s1w[1024], s1b[512], s2[512 * 8];
    int tid = threadIdx.x;
#pragma unroll
    for (int i = 0; i < 4; i++) s1w[tid + i * 256] = c1w[tid + i * 256];
#pragma unroll
    for (int i = 0; i < 2; i++) s1b[tid + i * 256] = c1b[tid + i * 256];
#pragma unroll
    for (int i = 0; i < 16; i++) {
        int idx = tid + i * 256;
        int j = idx >> 3, h = idx & 7;
        s2[idx] = c2w[h * 512 + j];
    }
    __syncthreads();
    int t = blockIdx.x * 256 + tid;
    if (t >= T || t >= 32768) return;
    float t0 = tab[2 * t], t1 = tab[2 * t + 1];
    float acc[8];
#pragma unroll
    for (int h = 0; h < 8; h++) acc[h] = 0.f;
    for (int j = 0; j < 512; j++) {
        float hv = fmaxf(t0 * s1w[2 * j] + t1 * s1w[2 * j + 1] + s1b[j], 0.f);
#pragma unroll
        for (int h = 0; h < 8; h++) acc[h] += hv * s2[j * 8 + h];
    }
#pragma unroll
    for (int h = 0; h < 8; h++) g_cpb[t * 8 + h] = acc[h] + c2b[h];
}

// ---------------- conv 3x3 as implicit GEMM (3xBF16 m16n8k16) ----------------
__global__ void __launch_bounds__(256) k_conv_tc(const float* __restrict__ x,
                                                 const float* __restrict__ bias) {
    extern __shared__ float sm[];
    unsigned* u_xh = (unsigned*)sm;
    unsigned* u_xl = u_xh + 2240;
    unsigned* u_wh = u_xl + 2240;
    unsigned* u_wl = u_wh + 5184;

    int b = blockIdx.x >> 5;
    int y0 = (blockIdx.x & 31) * 2;
    int ocg = blockIdx.y;
    int tid = threadIdx.x;
    int wid = tid >> 5, lane = tid & 31;
    int g = lane >> 2, tcol = lane & 3;
    int wm0 = (wid >> 1) * 32, wn0 = (wid & 1) * 32;

    float acc[2][4][4];
#pragma unroll
    for (int a = 0; a < 2; a++)
#pragma unroll
        for (int bq = 0; bq < 4; bq++)
#pragma unroll
            for (int c = 0; c < 4; c++) acc[a][bq][c] = 0.f;

    const float* xb = x + (size_t)b * 192 * 4096;

    for (int cc = 0; cc < 12; cc++) {
        int c0 = cc * 16;
#pragma unroll
        for (int i = 0; i < 2; i++) {
            int f = tid + i * 256;
            int p = f >> 6;
            int rem = f & 63;
            int r = rem >> 4, seg = rem & 15;
            int gy = y0 - 1 + r;
            float4 v0 = make_float4(0.f, 0.f, 0.f, 0.f);
            float4 v1 = make_float4(0.f, 0.f, 0.f, 0.f);
            if (gy >= 0 && gy < 64) {
                v0 = *(const float4*)(xb + ((size_t)(c0 + 2 * p) * 64 + gy) * 64 + seg * 4);
                v1 = *(const float4*)(xb + ((size_t)(c0 + 2 * p + 1) * 64 + gy) * 64 + seg * 4);
            }
            int off = p * 280 + r * 68 + 1 + seg * 4;
            float h0, l0, h1, l1;
            split_bf(v0.x, h0, l0); split_bf(v1.x, h1, l1);
            u_xh[off + 0] = pack_bf(h0, h1); u_xl[off + 0] = pack_bf(l0, l1);
            split_bf(v0.y, h0, l0); split_bf(v1.y, h1, l1);
            u_xh[off + 1] = pack_bf(h0, h1); u_xl[off + 1] = pack_bf(l0, l1);
            split_bf(v0.z, h0, l0); split_bf(v1.z, h1, l1);
            u_xh[off + 2] = pack_bf(h0, h1); u_xl[off + 2] = pack_bf(l0, l1);
            split_bf(v0.w, h0, l0); split_bf(v1.w, h1, l1);
            u_xh[off + 3] = pack_bf(h0, h1); u_xl[off + 3] = pack_bf(l0, l1);
        }
        if (tid < 64) {
            int p = tid >> 3;
            int rr = tid & 7;
            int r = rr >> 1, side = rr & 1;
            int off = p * 280 + r * 68 + (side ? 65 : 0);
            u_xh[off] = 0u; u_xl[off] = 0u;
        }
#pragma unroll
        for (int i = 0; i < 5; i++) {
            int f = tid + i * 256;
            if (f < 1152) {
                int krow = f >> 4, seg = f & 15;
                size_t src = ((size_t)(cc * 72) + krow) * 192 + ocg * 64 + seg * 4;
                int off = krow * 72 + seg * 4;
                *(uint4*)(u_wh + off) = *(const uint4*)(g_Wcph + src);
                *(uint4*)(u_wl + off) = *(const uint4*)(g_Wcpl + src);
            }
        }
        __syncthreads();

#pragma unroll
        for (int t = 0; t < 9; t++) {
            int dh = t / 3, dw = t - dh * 3;
            unsigned bh[4][2], bl[4][2];
#pragma unroll
            for (int nt = 0; nt < 4; nt++) {
                int o = wn0 + nt * 8 + g;
                int kr0 = (t * 8 + tcol) * 72 + o;
                int kr1 = (t * 8 + tcol + 4) * 72 + o;
                bh[nt][0] = u_wh[kr0];
                bl[nt][0] = u_wl[kr0];
                bh[nt][1] = u_wh[kr1];
                bl[nt][1] = u_wl[kr1];
            }
#pragma unroll
            for (int mt = 0; mt < 2; mt++) {
                int mbase = wm0 + mt * 16;
                int rA = (mbase >> 6) + dh;
                int col0 = (mbase & 63) + g + dw;
                int base0 = tcol * 280 + rA * 68 + col0;
                int base1 = (tcol + 4) * 280 + rA * 68 + col0;
                unsigned ah[4], al[4];
                ah[0] = u_xh[base0];
                ah[1] = u_xh[base0 + 8];
                ah[2] = u_xh[base1];
                ah[3] = u_xh[base1 + 8];
                al[0] = u_xl[base0];
                al[1] = u_xl[base0 + 8];
                al[2] = u_xl[base1];
                al[3] = u_xl[base1 + 8];
#pragma unroll
                for (int nt = 0; nt < 4; nt++) {
                    mma16bf(acc[mt][nt], al, bh[nt]);
                    mma16bf(acc[mt][nt], ah, bl[nt]);
                    mma16bf(acc[mt][nt], ah, bh[nt]);
                }
            }
        }
        __syncthreads();
    }
    const float* bb = bias + ocg * 64;
    size_t rowbase = (size_t)b * 4096 + (size_t)y0 * 64;
#pragma unroll
    for (int mt = 0; mt < 2; mt++) {
#pragma unroll
        for (int nt = 0; nt < 4; nt++) {
            int r0 = wm0 + mt * 16 + g;
            int cc2 = wn0 + nt * 8 + 2 * tcol;
            float b0v = bb[cc2], b1v = bb[cc2 + 1];
            float* o0 = g_xc + (rowbase + r0) * 192 + ocg * 64 + cc2;
            o0[0] = acc[mt][nt][0] + b0v;
            o0[1] = acc[mt][nt][1] + b1v;
            float* o1 = g_xc + (rowbase + r0 + 8) * 192 + ocg * 64 + cc2;
            o1[0] = acc[mt][nt][2] + b0v;
            o1[1] = acc[mt][nt][3] + b1v;
        }
    }
}

// ---------------- row LN ----------------
__global__ void k_ln_rows(const float* __restrict__ gam, const float* __restrict__ bet) {
    int row = blockIdx.x * 8 + (threadIdx.x >> 5);
    int lane = threadIdx.x & 31;
    const float* src = g_xc + (size_t)row * 192;
    float v[6];
    float s = 0.f, q = 0.f;
#pragma unroll
    for (int j = 0; j < 6; j++) {
        v[j] = src[lane + j * 32];
        s += v[j]; q += v[j] * v[j];
    }
#pragma unroll
    for (int off = 16; off; off >>= 1) {
        s += __shfl_xor_sync(0xffffffffu, s, off);
        q += __shfl_xor_sync(0xffffffffu, q, off);
    }
    float mean = s * (1.f / 192.f);
    float rstd = rsqrtf(q * (1.f / 192.f) - mean * mean + 1e-5f);
    float* dst = g_t + (size_t)row * 192;
#pragma unroll
    for (int j = 0; j < 6; j++) {
        int c = lane + j * 32;
        dst[c] = (v[j] - mean) * rstd * gam[c] + bet[c];
    }
}

// ---------------- generic GEMM (3xBF16 m16n8k16; W pre-packed) ----------------
template <int BN>
__global__ void __launch_bounds__(256) k_gemm_tc(const float* __restrict__ A,
                                                 const unsigned* __restrict__ Wph,
                                                 const unsigned* __restrict__ Wpl,
                                                 const float* __restrict__ bias,
                                                 float* __restrict__ C,
                                                 int M, int Nout) {
    constexpr int NT = BN / 16;
    extern __shared__ unsigned smu[];
    unsigned* Ash = smu;
    unsigned* Asl = Ash + 2560;
    unsigned* Wsh = Asl + 2560;
    unsigned* Wsl = Wsh + BN * 20;
    int m0 = blockIdx.x * 128, n0 = blockIdx.y * BN;
    int tid = threadIdx.x, wid = tid >> 5, lane = tid & 31;
    int g = lane >> 2, tcol = lane & 3;
    int wm0 = (wid >> 1) * 32, wn0 = (wid & 1) * (BN / 2);
    float acc[2][NT][4];
#pragma unroll
    for (int a = 0; a < 2; a++)
#pragma unroll
        for (int b = 0; b < NT; b++)
#pragma unroll
            for (int c = 0; c < 4; c++) acc[a][b][c] = 0.f;

    for (int kc = 0; kc < 192; kc += 32) {
#pragma unroll
        for (int i = 0; i < 4; i++) {
            int f = tid + i * 256;
            int row = f >> 3, seg = f & 7;
            float4 v = *(const float4*)(A + (size_t)(m0 + row) * 192 + kc + seg * 4);
            float h0, l0, h1, l1;
            int off = row * 20 + seg * 2;
            split_bf(v.x, h0, l0); split_bf(v.y, h1, l1);
            Ash[off] = pack_bf(h0, h1); Asl[off] = pack_bf(l0, l1);
            split_bf(v.z, h0, l0); split_bf(v.w, h1, l1);
            Ash[off + 1] = pack_bf(h0, h1); Asl[off + 1] = pack_bf(l0, l1);
        }
#pragma unroll
        for (int i = 0; i < (BN * 4 + 255) / 256; i++) {
            int f = tid + i * 256;
            if (f < BN * 4) {
                int row = f >> 2, seg = f & 3;
                size_t src = (size_t)(n0 + row) * 96 + (kc >> 1) + seg * 4;
                uint4 vh = *(const uint4*)(Wph + src);
                uint4 vl = *(const uint4*)(Wpl + src);
                int off = row * 20 + seg * 4;
                Wsh[off + 0] = vh.x; Wsh[off + 1] = vh.y; Wsh[off + 2] = vh.z; Wsh[off + 3] = vh.w;
                Wsl[off + 0] = vl.x; Wsl[off + 1] = vl.y; Wsl[off + 2] = vl.z; Wsl[off + 3] = vl.w;
            }
        }
        __syncthreads();
#pragma unroll
        for (int kk8 = 0; kk8 < 16; kk8 += 8) {
            unsigned bh[NT][2], bl[NT][2];
#pragma unroll
            for (int nt = 0; nt < NT; nt++) {
                int wr = (wn0 + nt * 8 + g) * 20;
                bh[nt][0] = Wsh[wr + kk8 + tcol];
                bl[nt][0] = Wsl[wr + kk8 + tcol];
                bh[nt][1] = Wsh[wr + kk8 + tcol + 4];
                bl[nt][1] = Wsl[wr + kk8 + tcol + 4];
            }
#pragma unroll
            for (int mt = 0; mt < 2; mt++) {
                int r = wm0 + mt * 16 + g;
                int ar = r * 20, ar8 = (r + 8) * 20;
                unsigned ah[4], al[4];
                ah[0] = Ash[ar + kk8 + tcol];
                ah[1] = Ash[ar8 + kk8 + tcol];
                ah[2] = Ash[ar + kk8 + tcol + 4];
                ah[3] = Ash[ar8 + kk8 + tcol + 4];
                al[0] = Asl[ar + kk8 + tcol];
                al[1] = Asl[ar8 + kk8 + tcol];
                al[2] = Asl[ar + kk8 + tcol + 4];
                al[3] = Asl[ar8 + kk8 + tcol + 4];
#pragma unroll
                for (int nt = 0; nt < NT; nt++) {
                    mma16bf(acc[mt][nt], al, bh[nt]);
                    mma16bf(acc[mt][nt], ah, bl[nt]);
                    mma16bf(acc[mt][nt], ah, bh[nt]);
                }
            }
        }
        __syncthreads();
    }
#pragma unroll
    for (int mt = 0; mt < 2; mt++)
#pragma unroll
        for (int nt = 0; nt < NT; nt++) {
            int r = m0 + wm0 + mt * 16 + g;
            int cc = n0 + wn0 + nt * 8 + 2 * tcol;
            float b0v = bias[cc], b1v = bias[cc + 1];
            C[(size_t)r * Nout + cc]           = acc[mt][nt][0] + b0v;
            C[(size_t)r * Nout + cc + 1]       = acc[mt][nt][1] + b1v;
            C[(size_t)(r + 8) * Nout + cc]     = acc[mt][nt][2] + b0v;
            C[(size_t)(r + 8) * Nout + cc + 1] = acc[mt][nt][3] + b1v;
        }
}

// ---------------- fused post ----------------
__global__ void k_post(const float* __restrict__ qe, const float* __restrict__ temp,
                       const float* __restrict__ seqscale) {
    int idx = blockIdx.x * 256 + threadIdx.x;
    int g = idx % 24;
    int bn = idx / 24;
    int n = bn & 4095; int b = bn >> 12;
    if (g < 8) {
        int h = g;
        const float4* q4 = (const float4*)(g_qkvs + (size_t)bn * 768 + h * 24);
        float v[24]; float s = 0.f;
#pragma unroll
        for (int i = 0; i < 6; i++) {
            float4 t = q4[i];
            v[4 * i] = t.x; v[4 * i + 1] = t.y; v[4 * i + 2] = t.z; v[4 * i + 3] = t.w;
        }
#pragma unroll
        for (int d = 0; d < 24; d++) s += v[d] * v[d];
        float rn = 1.f / fmaxf(sqrtf(s), 1e-12f);
        float sp = log1pf(expf(temp[h]));
        float ss = seqscale[n];
        size_t ob = ((size_t)(b * 8 + h) * 4096 + n) * 24;
        float qn[24];
        float4* qs4 = (float4*)(g_qs + ob);
#pragma unroll
        for (int i = 0; i < 6; i++) {
            float4 c;
            float a0 = v[4 * i] * rn, a1 = v[4 * i + 1] * rn;
            float a2 = v[4 * i + 2] * rn, a3 = v[4 * i + 3] * rn;
            c.x = (a0 + qe[h * 24 + 4 * i])     * sp * ss;
            c.y = (a1 + qe[h * 24 + 4 * i + 1]) * sp * ss;
            c.z = (a2 + qe[h * 24 + 4 * i + 2]) * sp * ss;
            c.w = (a3 + qe[h * 24 + 4 * i + 3]) * sp * ss;
            qs4[i] = c;
            qn[4 * i] = a0; qn[4 * i + 1] = a1; qn[4 * i + 2] = a2; qn[4 * i + 3] = a3;
        }
        size_t ob2 = ((size_t)(b * 8 + h) * 4096 + n) * 12;
        const float* ltr = g_lt2 + h * 216;
#pragma unroll
        for (int l = 0; l < 9; l++) {
            float p = 0.f;
#pragma unroll
            for (int d = 0; d < 24; d++) p += qn[d] * ltr[l * 24 + d];
            g_w2[ob2 + l] = p;
        }
    } else {
        int gg = g - 8;
        const float4* src4 = (const float4*)(g_qkvs + (size_t)bn * 768 + 192 + gg * 24);
        float v[24]; float s = 0.f;
#pragma unroll
        for (int i = 0; i < 6; i++) {
            float4 t = src4[i];
            v[4 * i] = t.x; v[4 * i + 1] = t.y; v[4 * i + 2] = t.z; v[4 * i + 3] = t.w;
        }
#pragma unroll
        for (int d = 0; d < 24; d++) s += v[d] * v[d];
        float rn = 1.f;
        if (gg < 8) rn = 1.f / fmaxf(sqrtf(s), 1e-12f);
        size_t ob = ((size_t)(b * 16 + gg) * 4096 + n) * 24;
        float4* dst4 = (float4*)(g_kvmap + ob);
#pragma unroll
        for (int i = 0; i < 6; i++) {
            float4 o;
            o.x = v[4 * i] * rn; o.y = v[4 * i + 1] * rn;
            o.z = v[4 * i + 2] * rn; o.w = v[4 * i + 3] * rn;
            dst4[i] = o;
        }
    }
}

// ---------------- gelu + 4x4 pool + LN ----------------
__global__ void k_pool(const float* __restrict__ ng, const float* __restrict__ nb) {
    __shared__ float r1[192], r2[192];
    int b = blockIdx.y, m = blockIdx.x;
    int c = threadIdx.x;
    int ph = m >> 4, pw = m & 15;
    float acc = 0.f;
#pragma unroll
    for (int i = 0; i < 4; i++)
#pragma unroll
        for (int j = 0; j < 4; j++) {
            int n = (ph * 4 + i) * 64 + pw * 4 + j;
            float v = g_qkvs[((size_t)(b * 4096 + n)) * 768 + 576 + c];
            acc += 0.5f * v * (1.f + erff(v * 0.70710678118654752f));
        }
    acc *= (1.f / 16.f);
    r1[c] = acc; r2[c] = acc * acc;
    __syncthreads();
    if (c < 64) { r1[c] += r1[c + 64] + r1[c + 128]; r2[c] += r2[c + 64] + r2[c + 128]; }
    __syncthreads();
    for (int s2 = 32; s2 > 0; s2 >>= 1) {
        if (c < s2) { r1[c] += r1[c + s2]; r2[c] += r2[c + s2]; }
        __syncthreads();
    }
    float mean = r1[0] * (1.f / 192.f);
    float var = r2[0] * (1.f / 192.f) - mean * mean;
    float rstd = rsqrtf(var + 1e-5f);
    g_pooled[((size_t)(b * 256 + m)) * 192 + c] = (acc - mean) * rstd * ng[c] + nb[c];
}

// ---------------- post pooled kv ----------------
__global__ void k_postkvp() {
    int idx = blockIdx.x * 256 + threadIdx.x;
    int g = idx & 15; int bm = idx >> 4;
    int m = bm & 255; int b = bm >> 8;
    const float4* src4 = (const float4*)(g_kvp + (size_t)bm * 384 + g * 24);
    float v[24]; float s = 0.f;
#pragma unroll
    for (int i = 0; i < 6; i++) {
        float4 t = src4[i];
        v[4 * i] = t.x; v[4 * i + 1] = t.y; v[4 * i + 2] = t.z; v[4 * i + 3] = t.w;
    }
#pragma unroll
    for (int d = 0; d < 24; d++) s += v[d] * v[d];
    if (g < 8) {
        float rn = 1.f / fmaxf(sqrtf(s), 1e-12f);
        float4* dst4 = (float4*)(g_kpn + ((size_t)(b * 8 + g) * 256 + m) * 24);
#pragma unroll
        for (int i = 0; i < 6; i++) {
            float4 o;
            o.x = v[4 * i] * rn; o.y = v[4 * i + 1] * rn;
            o.z = v[4 * i + 2] * rn; o.w = v[4 * i + 3] * rn;
            dst4[i] = o;
        }
    } else {
        float4* dst4 = (float4*)(g_vpn + ((size_t)(b * 8 + g - 8) * 256 + m) * 24);
#pragma unroll
        for (int i = 0; i < 6; i++) {
            float4 o;
            o.x = v[4 * i]; o.y = v[4 * i + 1]; o.z = v[4 * i + 2]; o.w = v[4 * i + 3];
            dst4[i] = o;
        }
    }
}

// ---------------- fused attention (2 q/warp; f32x2 dots; deferred normalization) ----------------
__global__ void __launch_bounds__(256) k_attn(const int* __restrict__ rel_idx,
                                              const float* __restrict__ rpb,
                                              const float* __restrict__ lb) {
    extern __shared__ float sm[];
    float* sk  = sm;
    float* skp = sk + 7776;
    float* svp = skp + 7168;
    float* slog = svp + 6240;
    float* srpb = slog + 4736;
    float* slb = srpb + 16;

    int b = blockIdx.z, h = blockIdx.y;
    int Y0 = (blockIdx.x >> 2) * 16, X0 = (blockIdx.x & 3) * 16;
    int tid = threadIdx.x;

    const float* kbase = g_kvmap + ((size_t)(b * 16 + h) * 4096) * 24;
    const float* vbase = g_kvmap + ((size_t)(b * 16 + 8 + h) * 4096) * 24;
    for (int f = tid; f < 1944; f += 256) {
        int r = f / 6, q = f - r * 6;
        int xx = r % 18, yy = r / 18;
        int gy = Y0 - 1 + yy, gx = X0 - 1 + xx;
        float4 v = make_float4(0.f, 0.f, 0.f, 0.f);
        if (gy >= 0 && gy < 64 && gx >= 0 && gx < 64)
            v = *(const float4*)(kbase + (size_t)(gy * 64 + gx) * 24 + q * 4);
        *(float4*)(sk + r * 24 + q * 4) = v;
    }
    const float* kp = g_kpn + (size_t)(b * 8 + h) * 256 * 24;
    const float* vp = g_vpn + (size_t)(b * 8 + h) * 256 * 24;
    for (int f = tid; f < 1536; f += 256) {
        int m = f / 6, q = f - m * 6;
        *(float4*)(skp + m * 28 + q * 4) = *(const float4*)(kp + m * 24 + q * 4);
    }
    for (int f = tid; f < 1024; f += 256) {
        int m = f >> 2, d = 24 + (f & 3);
        skp[m * 28 + d] = 0.f;
    }
    for (int f = tid; f < 1536; f += 256) {
        int m = f / 6, q = f - m * 6;
        float4 v = *(const float4*)(vp + (size_t)m * 24 + q * 4);
        svp[(q * 4 + 0) * 260 + m] = v.x;
        svp[(q * 4 + 1) * 260 + m] = v.y;
        svp[(q * 4 + 2) * 260 + m] = v.z;
        svp[(q * 4 + 3) * 260 + m] = v.w;
    }
    for (int f = tid; f < 96; f += 256) {
        int d = f >> 2, m = 256 + (f & 3);
        svp[d * 260 + m] = 0.f;
    }
    if (tid < 9) { srpb[tid] = rpb[h * 9 + tid]; slb[tid] = lb[h * 9 + tid]; }
    __syncthreads();

    int w = tid >> 5, ln = tid & 31;
    float* mylogA = slog + w * 296;   // [0..8] raw local e, [12..20] w2+lb, [32..287] raw pool e
    float* mylogB = slog + (8 + w) * 296;
    const unsigned FULL = 0xffffffffu;
    size_t bh4096 = (size_t)(b * 8 + h) * 4096;

    for (int it = 0; it < 16; it++) {
        int qiA = it * 16 + w;
        int qiB = qiA + 8;
        int tyA = qiA >> 4, txA = qiA & 15;
        int tyB = qiB >> 4, txB = qiB & 15;
        int gyA = Y0 + tyA, gxA = X0 + txA;
        int gyB = Y0 + tyB, gxB = X0 + txB;
        int nA = gyA * 64 + gxA, nB = gyB * 64 + gxB;

        float qsA = 0.f, qsB = 0.f;
        if (ln < 24) {
            qsA = g_qs[(bh4096 + nA) * 24 + ln];
            qsB = g_qs[(bh4096 + nB) * 24 + ln];
        }
        // packed q pairs (d, d+1) via shfl broadcast
        u64 qpA[12], qpB[12];
#pragma unroll
        for (int d = 0; d < 12; d++) {
            float a0 = __shfl_sync(FULL, qsA, 2 * d);
            float a1 = __shfl_sync(FULL, qsA, 2 * d + 1);
            float b0 = __shfl_sync(FULL, qsB, 2 * d);
            float b1 = __shfl_sync(FULL, qsB, 2 * d + 1);
            qpA[d] = packf2(a0, a1);
            qpB[d] = packf2(b0, b1);
        }

        // lane-parallel local logits: lanes 0..8 -> A, lanes 16..24 -> B
        float w2v = 0.f;
        if (ln < 9) {
            w2v = g_w2[(bh4096 + nA) * 12 + ln];
            int dh = ln / 3 - 1, dw = ln % 3 - 1;
            bool lvalid = (gyA + dh >= 0) && (gyA + dh < 64) && (gxA + dw >= 0) && (gxA + dw < 64);
            const ulonglong2* kp2 = (const ulonglong2*)(sk + ((tyA + 1 + dh) * 18 + (txA + 1 + dw)) * 24);
            ulonglong2 c0 = kp2[0], c1 = kp2[1], c2 = kp2[2];
            ulonglong2 c3 = kp2[3], c4 = kp2[4], c5 = kp2[5];
            u64 acc = 0ULL;
            ffma2(acc, qpA[0], c0.x);  ffma2(acc, qpA[1], c0.y);
            ffma2(acc, qpA[2], c1.x);  ffma2(acc, qpA[3], c1.y);
            ffma2(acc, qpA[4], c2.x);  ffma2(acc, qpA[5], c2.y);
            ffma2(acc, qpA[6], c3.x);  ffma2(acc, qpA[7], c3.y);
            ffma2(acc, qpA[8], c4.x);  ffma2(acc, qpA[9], c4.y);
            ffma2(acc, qpA[10], c5.x); ffma2(acc, qpA[11], c5.y);
            float2 f2 = unpackf2(acc);
            mylogA[ln] = lvalid ? (f2.x + f2.y + srpb[ln]) : -1e30f;
        } else if (ln >= 16 && ln < 25) {
            int l = ln - 16;
            w2v = g_w2[(bh4096 + nB) * 12 + l];
            int dh = l / 3 - 1, dw = l % 3 - 1;
            bool lvalid = (gyB + dh >= 0) && (gyB + dh < 64) && (gxB + dw >= 0) && (gxB + dw < 64);
            const ulonglong2* kp2 = (const ulonglong2*)(sk + ((tyB + 1 + dh) * 18 + (txB + 1 + dw)) * 24);
            ulonglong2 c0 = kp2[0], c1 = kp2[1], c2 = kp2[2];
            ulonglong2 c3 = kp2[3], c4 = kp2[4], c5 = kp2[5];
            u64 acc = 0ULL;
            ffma2(acc, qpB[0], c0.x);  ffma2(acc, qpB[1], c0.y);
            ffma2(acc, qpB[2], c1.x);  ffma2(acc, qpB[3], c1.y);
            ffma2(acc, qpB[4], c2.x);  ffma2(acc, qpB[5], c2.y);
            ffma2(acc, qpB[6], c3.x);  ffma2(acc, qpB[7], c3.y);
            ffma2(acc, qpB[8], c4.x);  ffma2(acc, qpB[9], c4.y);
            ffma2(acc, qpB[10], c5.x); ffma2(acc, qpB[11], c5.y);
            float2 f2 = unpackf2(acc);
            mylogB[l] = lvalid ? (f2.x + f2.y + srpb[l]) : -1e30f;
        }

        // pool logits: packed f32x2 dots, shared K row for both queries
        const int* riA = rel_idx + (size_t)nA * 256;
        const int* riB = rel_idx + (size_t)nB * 256;
#pragma unroll
        for (int bm = 0; bm < 8; bm++) {
            int m = bm * 32 + ln;
            float cA = g_cpb[(size_t)riA[m] * 8 + h];
            float cB = g_cpb[(size_t)riB[m] * 8 + h];
            const ulonglong2* rp = (const ulonglong2*)(skp + m * 28);
            ulonglong2 r0 = rp[0], r1 = rp[1], r2 = rp[2];
            ulonglong2 r3 = rp[3], r4 = rp[4], r5 = rp[5];
            u64 accA = 0ULL, accB = 0ULL;
            ffma2(accA, qpA[0], r0.x);  ffma2(accB, qpB[0], r0.x);
            ffma2(accA, qpA[1], r0.y);  ffma2(accB, qpB[1], r0.y);
            ffma2(accA, qpA[2], r1.x);  ffma2(accB, qpB[2], r1.x);
            ffma2(accA, qpA[3], r1.y);  ffma2(accB, qpB[3], r1.y);
            ffma2(accA, qpA[4], r2.x);  ffma2(accB, qpB[4], r2.x);
            ffma2(accA, qpA[5], r2.y);  ffma2(accB, qpB[5], r2.y);
            ffma2(accA, qpA[6], r3.x);  ffma2(accB, qpB[6], r3.x);
            ffma2(accA, qpA[7], r3.y);  ffma2(accB, qpB[7], r3.y);
            ffma2(accA, qpA[8], r4.x);  ffma2(accB, qpB[8], r4.x);
            ffma2(accA, qpA[9], r4.y);  ffma2(accB, qpB[9], r4.y);
            ffma2(accA, qpA[10], r5.x); ffma2(accB, qpB[10], r5.x);
            ffma2(accA, qpA[11], r5.y); ffma2(accB, qpB[11], r5.y);
            float2 fa = unpackf2(accA);
            float2 fb = unpackf2(accB);
            mylogA[32 + m] = fa.x + fa.y + cA;
            mylogB[32 + m] = fb.x + fb.y + cB;
        }
        __syncwarp();

        // prefetch local V taps
        float vA[9], vB[9];
        if (ln < 24) {
#pragma unroll
            for (int l = 0; l < 9; l++) {
                int dh = l / 3 - 1, dw = l % 3 - 1;
                int nyA = gyA + dh, nxA = gxA + dw;
                vA[l] = (nyA >= 0 && nyA < 64 && nxA >= 0 && nxA < 64)
                        ? vbase[(size_t)(nyA * 64 + nxA) * 24 + ln] : 0.f;
                int nyB = gyB + dh, nxB = gxB + dw;
                vB[l] = (nyB >= 0 && nyB < 64 && nxB >= 0 && nxB < 64)
                        ? vbase[(size_t)(nyB * 64 + nxB) * 24 + ln] : 0.f;
            }
        }

        // softmax: max + exp (store raw e); normalization deferred to epilogue
        float mxA = -1e30f, mxB = -1e30f;
#pragma unroll
        for (int j = 0; j < 8; j++) {
            mxA = fmaxf(mxA, mylogA[32 + j * 32 + ln]);
            mxB = fmaxf(mxB, mylogB[32 + j * 32 + ln]);
        }
        if (ln < 9) {
            mxA = fmaxf(mxA, mylogA[ln]);
            mxB = fmaxf(mxB, mylogB[ln]);
        }
#pragma unroll
        for (int off = 16; off > 0; off >>= 1) {
            mxA = fmaxf(mxA, __shfl_xor_sync(FULL, mxA, off));
            mxB = fmaxf(mxB, __shfl_xor_sync(FULL, mxB, off));
        }
        float sumA = 0.f, sumB = 0.f;
#pragma unroll
        for (int j = 0; j < 8; j++) {
            int i = 32 + j * 32 + ln;
            float eA = expf(mylogA[i] - mxA); mylogA[i] = eA; sumA += eA;
            float eB = expf(mylogB[i] - mxB); mylogB[i] = eB; sumB += eB;
        }
        if (ln < 9) {
            float e = expf(mylogA[ln] - mxA);
            mylogA[ln] = e;
            mylogA[12 + ln] = w2v + slb[ln];
            sumA += e;
        } else if (ln >= 16 && ln < 25) {
            int l = ln - 16;
            float e = expf(mylogB[l] - mxB);
            mylogB[l] = e;
            mylogB[12 + l] = w2v + slb[l];
            sumB += e;
        }
#pragma unroll
        for (int off = 16; off > 0; off >>= 1) {
            sumA += __shfl_xor_sync(FULL, sumA, off);
            sumB += __shfl_xor_sync(FULL, sumB, off);
        }
        float invA = 1.f / sumA, invB = 1.f / sumB;
        __syncwarp();

        if (ln < 24) {
            // local: Sum (w2+lb)·v  +  inv·Sum e·v ; pool folded into the inv term
            float lwA = 0.f, lwB = 0.f, leA = 0.f, leB = 0.f;
#pragma unroll
            for (int l = 0; l < 9; l++) {
                lwA += mylogA[12 + l] * vA[l];
                leA += mylogA[l] * vA[l];
                lwB += mylogB[12 + l] * vB[l];
                leB += mylogB[l] * vB[l];
            }
            const float* vrow = svp + ln * 260;
            u64 pA0 = 0ULL, pA1 = 0ULL, pB0 = 0ULL, pB1 = 0ULL;
#pragma unroll
            for (int m = 0; m < 256; m += 8) {
                const ulonglong2* vp2 = (const ulonglong2*)(vrow + m);
                ulonglong2 v0 = vp2[0], v1 = vp2[1];
                const ulonglong2* wA2 = (const ulonglong2*)(mylogA + 32 + m);
                const ulonglong2* wB2 = (const ulonglong2*)(mylogB + 32 + m);
                ulonglong2 a0 = wA2[0], a1 = wA2[1];
                ulonglong2 b0 = wB2[0], b1 = wB2[1];
                ffma2(pA0, a0.x, v0.x); ffma2(pB0, b0.x, v0.x);
                ffma2(pA0, a0.y, v0.y); ffma2(pB0, b0.y, v0.y);
                ffma2(pA1, a1.x, v1.x); ffma2(pB1, b1.x, v1.x);
                ffma2(pA1, a1.y, v1.y); ffma2(pB1, b1.y, v1.y);
            }
            float2 fA0 = unpackf2(pA0), fA1 = unpackf2(pA1);
            float2 fB0 = unpackf2(pB0), fB1 = unpackf2(pB1);
            float poolA = (fA0.x + fA0.y) + (fA1.x + fA1.y);
            float poolB = (fB0.x + fB0.y) + (fB1.x + fB1.y);
            g_ao[((size_t)(b * 4096 + nA)) * 192 + h * 24 + ln] = lwA + invA * (leA + poolA);
            g_ao[((size_t)(b * 4096 + nB)) * 192 + h * 24 + ln] = lwB + invB * (leB + poolB);
        }
        __syncwarp();
    }
}

// ---------------- final LN + transpose to (B,C,N) ----------------
__global__ void k_lnout(const float* __restrict__ gam, const float* __restrict__ bet,
                        float* __restrict__ out) {
    __shared__ float s[192 * 33];
    __shared__ float red[2][8][32];
    __shared__ float smean[32], srstd[32];
    int b = blockIdx.y, n0 = blockIdx.x * 32;
    int tx = threadIdx.x & 31, ty = threadIdx.x >> 5;
    for (int idx = threadIdx.x; idx < 32 * 192; idx += 256) {
        int i = idx / 192, c = idx - i * 192;
        s[c * 33 + i] = g_tmp[((size_t)(b * 4096 + n0 + i)) * 192 + c];
    }
    __syncthreads();
    float sum = 0.f, sq = 0.f;
    for (int c = ty; c < 192; c += 8) {
        float v = s[c * 33 + tx];
        sum += v; sq += v * v;
    }
    red[0][ty][tx] = sum; red[1][ty][tx] = sq;
    __syncthreads();
    if (ty == 0) {
        float s1 = 0.f, s2 = 0.f;
#pragma unroll
        for (int k = 0; k < 8; k++) { s1 += red[0][k][tx]; s2 += red[1][k][tx]; }
        float m = s1 * (1.f / 192.f);
        float var = s2 * (1.f / 192.f) - m * m;
        smean[tx] = m; srstd[tx] = rsqrtf(var + 1e-5f);
    }
    __syncthreads();
    for (int c = ty; c < 192; c += 8)
        out[(size_t)(b * 192 + c) * 4096 + n0 + tx] =
            (s[c * 33 + tx] - smean[tx]) * srstd[tx] * gam[c] + bet[c];
}

// ---------------- launch ----------------
extern "C" void kernel_launch(void* const* d_in, const int* in_sizes, int n_in,
                              void* d_out, int out_size) {
    const float* x      = (const float*)d_in[0];
    const float* pe_w   = (const float*)d_in[1];
    const float* pe_b   = (const float*)d_in[2];
    const float* pe_ln_g= (const float*)d_in[3];
    const float* pe_ln_b= (const float*)d_in[4];
    const float* q_w    = (const float*)d_in[5];
    const float* q_b    = (const float*)d_in[6];
    const float* kv_w   = (const float*)d_in[7];
    const float* kv_b   = (const float*)d_in[8];
    const float* sr_w   = (const float*)d_in[9];
    const float* sr_b   = (const float*)d_in[10];
    const float* norm_g = (const float*)d_in[11];
    const float* norm_b = (const float*)d_in[12];
    const float* cpb1_w = (const float*)d_in[13];
    const float* cpb1_b = (const float*)d_in[14];
    const float* cpb2_w = (const float*)d_in[15];
    const float* cpb2_b = (const float*)d_in[16];
    const float* rpb    = (const float*)d_in[17];
    const float* lt     = (const float*)d_in[18];
    const float* lb     = (const float*)d_in[19];
    const float* qe     = (const float*)d_in[20];
    const float* temp   = (const float*)d_in[21];
    const float* proj_w = (const float*)d_in[22];
    const float* proj_b = (const float*)d_in[23];
    const float* oln_g  = (const float*)d_in[24];
    const float* oln_b  = (const float*)d_in[25];
    const int*   relidx = (const int*)d_in[26];
    const float* ctab   = (const float*)d_in[27];
    const float* sscale = (const float*)d_in[28];
    float* out = (float*)d_out;

    int T = in_sizes[27] / 2;

    float *p_t, *p_qkvs, *p_pooled, *p_ao, *p_tmp, *p_bcat, *p_kvp;
    unsigned *p_Wfph, *p_Wfpl;
    cudaGetSymbolAddress((void**)&p_t, g_t);
    cudaGetSymbolAddress((void**)&p_qkvs, g_qkvs);
    cudaGetSymbolAddress((void**)&p_pooled, g_pooled);
    cudaGetSymbolAddress((void**)&p_kvp, g_kvp);
    cudaGetSymbolAddress((void**)&p_ao, g_ao);
    cudaGetSymbolAddress((void**)&p_tmp, g_tmp);
    cudaGetSymbolAddress((void**)&p_bcat, g_bcat);
    cudaGetSymbolAddress((void**)&p_Wfph, g_Wfph);
    cudaGetSymbolAddress((void**)&p_Wfpl, g_Wfpl);

    int attn_smem = 25952 * 4;
    int conv_smem = 14848 * 4;
    int gemm128_smem = (2560 * 2 + 128 * 20 * 2) * 4;
    int gemm64_smem  = (2560 * 2 + 64 * 20 * 2) * 4;

    static cudaStream_t s1 = nullptr;
    static cudaEvent_t evFork = nullptr, evGemm = nullptr, evJoin = nullptr;
    if (!s1) {
        cudaStreamCreateWithFlags(&s1, cudaStreamNonBlocking);
        cudaEventCreateWithFlags(&evFork, cudaEventDisableTiming);
        cudaEventCreateWithFlags(&evGemm, cudaEventDisableTiming);
        cudaEventCreateWithFlags(&evJoin, cudaEventDisableTiming);
        cudaFuncSetAttribute(k_attn, cudaFuncAttributeMaxDynamicSharedMemorySize, attn_smem);
        cudaFuncSetAttribute(k_conv_tc, cudaFuncAttributeMaxDynamicSharedMemorySize, conv_smem);
        cudaFuncSetAttribute(k_gemm_tc<128>, cudaFuncAttributeMaxDynamicSharedMemorySize, gemm128_smem);
        cudaFuncSetAttribute(k_gemm_tc<64>, cudaFuncAttributeMaxDynamicSharedMemorySize, gemm64_smem);
    }

    // fork: cpb table on s1 overlaps the conv chain
    cudaEventRecord(evFork, 0);
    cudaStreamWaitEvent(s1, evFork, 0);
    k_prep_cpb<<<(T + 255) / 256, 256, 0, s1>>>(ctab, cpb1_w, cpb1_b, cpb2_w, cpb2_b, T);

    k_prep<<<1296, 256>>>(q_w, q_b, kv_w, kv_b, sr_w, sr_b, proj_w, lt, pe_w);
    k_conv_tc<<<dim3(128, 3), 256, conv_smem>>>(x, pe_b);
    k_ln_rows<<<2048, 256>>>(pe_ln_g, pe_ln_b);
    k_gemm_tc<128><<<dim3(128, 6), 256, gemm128_smem>>>(p_t, p_Wfph, p_Wfpl, p_bcat, p_qkvs, 16384, 768);

    // fork: pool chain on s1 overlaps k_post on main
    cudaEventRecord(evGemm, 0);
    cudaStreamWaitEvent(s1, evGemm, 0);
    k_pool<<<dim3(256, 4), 192, 0, s1>>>(norm_g, norm_b);
    k_gemm_tc<128><<<dim3(8, 3), 256, gemm128_smem, s1>>>(p_pooled, p_Wfph + 192 * 96, p_Wfpl + 192 * 96, kv_b, p_kvp, 1024, 384);
    k_postkvp<<<64, 256, 0, s1>>>();
    cudaEventRecord(evJoin, s1);

    k_post<<<1536, 256>>>(qe, temp, sscale);

    // join before attention
    cudaStreamWaitEvent(0, evJoin, 0);
    k_attn<<<dim3(16, 8, 4), 256, attn_smem>>>(relidx, rpb, lb);
    k_gemm_tc<64><<<dim3(128, 3), 256, gemm64_smem>>>(p_ao, p_Wfph + 768 * 96, p_Wfpl + 768 * 96, proj_b, p_tmp, 16384, 192);
    k_lnout<<<dim3(128, 4), 256>>>(oln_g, oln_b, out);
}